// round 5
// baseline (speedup 1.0000x reference)
#include <cuda_runtime.h>
#include <cstdint>
#include <cstddef>

#define Vv   32000
#define Ee   1024
#define Hh   1024
#define Bb   32
#define SEe  256
#define SDd  128
#define G3   3072
#define NBLK 96

__device__ float g_enc_gi[(size_t)SEe * Bb * G3];
__device__ float g_dec_gx[(size_t)SDd * Bb * G3];
__device__ float g_enc_out[(size_t)SEe * Bb * Hh];
__device__ float g_kT[(size_t)Bb * SEe * Hh];
__device__ float g_dec_out[(size_t)SDd * Bb * Hh];
__device__ float g_h0[Bb * Hh];
__device__ float g_h1[Bb * Hh];
__device__ float g_ctx[Bb * Hh];
__device__ float g_q[Bb * Hh];
__device__ float g_sc[Bb * SEe];
__device__ float g_gh[Bb * G3];
__device__ float g_gc[Bb * G3];
__device__ int   g_enc_rows[SEe * Bb];
__device__ int   g_dec_rows[SDd * Bb];
__device__ unsigned g_bar_count;
__device__ unsigned g_bar_sense;

__device__ __forceinline__ float sigf(float x) { return 1.f / (1.f + expf(-x)); }

// software grid barrier: all NBLK blocks co-resident (NBLK <= 148 SMs, wave-1)
__device__ __forceinline__ void grid_bar(unsigned target)
{
    __syncthreads();
    if (threadIdx.x == 0) {
        __threadfence();
        if (atomicAdd(&g_bar_count, 1u) == NBLK - 1) {
            atomicExch(&g_bar_count, 0u);
            __threadfence();
            atomicExch(&g_bar_sense, target);
        } else {
            while (*(volatile unsigned*)&g_bar_sense < target) __nanosleep(64);
            __threadfence();
        }
    }
    __syncthreads();
}

__global__ void __launch_bounds__(256) build_rows_kernel(
    const int* __restrict__ enc_in, const int* __restrict__ dec_in)
{
    int m = blockIdx.x * 256 + threadIdx.x;
    if (m < SEe * Bb) {
        int t = m >> 5, b = m & 31;
        g_enc_rows[m] = enc_in[b * SEe + t];
    }
    if (m < SDd * Bb) {
        int t = m >> 5, b = m & 31;
        g_dec_rows[m] = dec_in[b * SDd + t];
    }
}

__global__ void __launch_bounds__(256) init_h_kernel()
{
    int i = blockIdx.x * 256 + threadIdx.x;
    if (i < Bb * Hh) g_h0[i] = 0.f;
}

// C[remap(m)][n] = bias[n] + sum_k A[arows?arows[m]:m][k] * W[n][k]
// BM=BN=128, BK=16, 256 threads, 8x8 microtile.
// Sremap>0: output row = (m&31)*Sremap + (m>>5)
__global__ void __launch_bounds__(256) gemm_nt(
    const float* __restrict__ A, const int* __restrict__ arows, int lda,
    const float* __restrict__ W, int ldw,
    const float* __restrict__ bias,
    float* __restrict__ C, int N, int K, int Sremap)
{
    __shared__ __align__(16) float As[16][132];
    __shared__ __align__(16) float Bs[16][132];
    int tid = threadIdx.x;
    int bm = blockIdx.y * 128, bn = blockIdx.x * 128;

    int lr = tid >> 2;
    int lk = (tid & 3) << 2;

    int r0 = bm + lr, r1 = bm + lr + 64;
    int ar0 = arows ? arows[r0] : r0;
    int ar1 = arows ? arows[r1] : r1;
    const float* arow0 = A + (size_t)ar0 * lda;
    const float* arow1 = A + (size_t)ar1 * lda;
    const float* wrow0 = W + (size_t)(bn + lr) * ldw;
    const float* wrow1 = W + (size_t)(bn + lr + 64) * ldw;

    int ty = tid >> 4;
    int tx = tid & 15;

    float acc[8][8];
#pragma unroll
    for (int i = 0; i < 8; i++)
#pragma unroll
        for (int j = 0; j < 8; j++) acc[i][j] = 0.f;

    for (int k0 = 0; k0 < K; k0 += 16) {
        float4 a0 = *(const float4*)(arow0 + k0 + lk);
        float4 a1 = *(const float4*)(arow1 + k0 + lk);
        float4 b0 = *(const float4*)(wrow0 + k0 + lk);
        float4 b1 = *(const float4*)(wrow1 + k0 + lk);
        __syncthreads();
        As[lk + 0][lr] = a0.x; As[lk + 1][lr] = a0.y; As[lk + 2][lr] = a0.z; As[lk + 3][lr] = a0.w;
        As[lk + 0][lr + 64] = a1.x; As[lk + 1][lr + 64] = a1.y; As[lk + 2][lr + 64] = a1.z; As[lk + 3][lr + 64] = a1.w;
        Bs[lk + 0][lr] = b0.x; Bs[lk + 1][lr] = b0.y; Bs[lk + 2][lr] = b0.z; Bs[lk + 3][lr] = b0.w;
        Bs[lk + 0][lr + 64] = b1.x; Bs[lk + 1][lr + 64] = b1.y; Bs[lk + 2][lr + 64] = b1.z; Bs[lk + 3][lr + 64] = b1.w;
        __syncthreads();
#pragma unroll
        for (int kk = 0; kk < 16; kk++) {
            float a[8], b[8];
            *(float4*)(a)     = *(const float4*)&As[kk][ty * 8];
            *(float4*)(a + 4) = *(const float4*)&As[kk][ty * 8 + 4];
            *(float4*)(b)     = *(const float4*)&Bs[kk][tx * 8];
            *(float4*)(b + 4) = *(const float4*)&Bs[kk][tx * 8 + 4];
#pragma unroll
            for (int i = 0; i < 8; i++)
#pragma unroll
                for (int j = 0; j < 8; j++) acc[i][j] += a[i] * b[j];
        }
    }

    int nbase = bn + tx * 8;
    float bj[8];
#pragma unroll
    for (int j = 0; j < 8; j++) bj[j] = bias ? bias[nbase + j] : 0.f;

#pragma unroll
    for (int i = 0; i < 8; i++) {
        int m = bm + ty * 8 + i;
        size_t orow = (Sremap > 0) ? ((size_t)(m & 31) * Sremap + (size_t)(m >> 5)) : (size_t)m;
        float* cp = C + orow * (size_t)N + nbase;
        float v[8];
#pragma unroll
        for (int j = 0; j < 8; j++) v[j] = acc[i][j] + bj[j];
        *(float4*)(cp)     = *(float4*)(v);
        *(float4*)(cp + 4) = *(float4*)(v + 4);
    }
}

// ---------------- persistent encoder: 256 GRU steps in one launch ----------------
__global__ void __launch_bounds__(256) enc_persistent(
    const float* __restrict__ Whh, const float* __restrict__ bhh,
    const int* __restrict__ enclen)
{
    int tid = threadIdx.x;
    __shared__ unsigned s_base;
    if (tid == 0) s_base = *(volatile unsigned*)&g_bar_sense;
    __syncthreads();
    unsigned ep = s_base;

    __shared__ __align__(16) float as[32][36];
    __shared__ __align__(16) float ws[32][36];

    int nb  = blockIdx.x * 32;     // this block's 32 output cols of 3072
    int col = tid & 31;
    int bq  = tid >> 5;            // batch group of 4
    int la_b = tid >> 3;
    int la_k = (tid & 7) << 2;
    int lw_r = tid >> 3;
    int lw_k = (tid & 7) << 2;
    const float* wbase = Whh + (size_t)(nb + lw_r) * Hh + lw_k;

    for (int t = 0; t < SEe; t++) {
        const float* h  = (t & 1) ? g_h1 : g_h0;
        float*       hn = (t & 1) ? g_h0 : g_h1;

        // phase A: gh[b][nb+col] = sum_k h[b][k] * Whh[nb+col][k]
        float acc[4] = {0.f, 0.f, 0.f, 0.f};
        const float* ap = h + (size_t)la_b * Hh + la_k;
        for (int k0 = 0; k0 < Hh; k0 += 32) {
            float4 av = *(const float4*)(ap + k0);
            float4 wv = *(const float4*)(wbase + k0);
            __syncthreads();
            as[la_k + 0][la_b] = av.x; as[la_k + 1][la_b] = av.y;
            as[la_k + 2][la_b] = av.z; as[la_k + 3][la_b] = av.w;
            ws[lw_k + 0][lw_r] = wv.x; ws[lw_k + 1][lw_r] = wv.y;
            ws[lw_k + 2][lw_r] = wv.z; ws[lw_k + 3][lw_r] = wv.w;
            __syncthreads();
#pragma unroll
            for (int kk = 0; kk < 32; kk++) {
                float w = ws[kk][col];
                float4 a4 = *(const float4*)&as[kk][bq << 2];
                acc[0] += w * a4.x; acc[1] += w * a4.y;
                acc[2] += w * a4.z; acc[3] += w * a4.w;
            }
        }
#pragma unroll
        for (int i = 0; i < 4; i++)
            g_gh[(size_t)(bq * 4 + i) * G3 + nb + col] = acc[i];

        grid_bar(++ep);

        // phase B: gate + state update + masked output
        for (int idx = blockIdx.x * 256 + tid; idx < Bb * Hh; idx += NBLK * 256) {
            int b = idx >> 10, j = idx & 1023;
            const float* gi = g_enc_gi + (size_t)(t * Bb + b) * G3;
            const float* gh = g_gh + (size_t)b * G3;
            float ghr = gh[j] + bhh[j];
            float ghz = gh[Hh + j] + bhh[Hh + j];
            float ghn = gh[2 * Hh + j] + bhh[2 * Hh + j];
            float r = sigf(gi[j] + ghr);
            float z = sigf(gi[Hh + j] + ghz);
            float n = tanhf(gi[2 * Hh + j] + r * ghn);
            float hold = h[idx];
            float hnv = (1.f - z) * n + z * hold;
            bool msk = t < enclen[b];
            hn[idx] = msk ? hnv : hold;
            g_enc_out[(size_t)t * Bb * Hh + idx] = msk ? hnv : 0.f;
        }
        grid_bar(++ep);
    }
}

// ---------------- persistent decoder: 128 attention+GRU steps in one launch ----------------
__global__ void __launch_bounds__(256) dec_persistent(
    const float* __restrict__ qW, const float* __restrict__ qb,
    const float* __restrict__ Whh, const float* __restrict__ Wih,  // full dec_Wih, ld = Ee+Hh
    const float* __restrict__ bhh)
{
    int tid = threadIdx.x, lane = tid & 31, warp = tid >> 5;
    int bid = blockIdx.x;
    __shared__ unsigned s_base;
    if (tid == 0) s_base = *(volatile unsigned*)&g_bar_sense;
    __syncthreads();
    unsigned ep = s_base;

    __shared__ __align__(16) float as[32][36];
    __shared__ __align__(16) float ws[32][72];
    __shared__ float sc[SEe];
    __shared__ float red[8];

    // P1 mapping (q, blocks 0..63, 16 cols each)
    int qnb   = bid * 16;
    int col16 = tid & 15;
    int bq16  = tid >> 4;           // 0..15, 2 batches each
    int lw_r16 = tid >> 4;          // 0..15
    int lw_k16 = (tid & 15) << 1;   // 0..30
    // shared A-chunk loaders
    int la_b = tid >> 3;
    int la_k = (tid & 7) << 2;
    // P4 mapping (64 cols per block)
    int j2 = tid & 31;
    int bg = tid >> 5;
    int lw_r64 = tid >> 2;          // 0..63
    int lw_k64 = (tid & 3) << 3;    // 0,8,16,24

    const float* Wc = Wih + Ee;     // ctx part of dec_Wih, row length 2048

    for (int t = 0; t < SDd; t++) {
        const float* h  = (t & 1) ? g_h1 : g_h0;
        float*       hn = (t & 1) ? g_h0 : g_h1;

        // ---- P1: q = h @ qW.T + qb  (blocks 0..63) ----
        if (bid < 64) {
            float acc[2] = {0.f, 0.f};
            const float* ap = h + (size_t)la_b * Hh + la_k;
            const float* wp = qW + (size_t)(qnb + lw_r16) * Hh + lw_k16;
            for (int k0 = 0; k0 < Hh; k0 += 32) {
                float4 av = *(const float4*)(ap + k0);
                float2 wv = *(const float2*)(wp + k0);
                __syncthreads();
                as[la_k + 0][la_b] = av.x; as[la_k + 1][la_b] = av.y;
                as[la_k + 2][la_b] = av.z; as[la_k + 3][la_b] = av.w;
                ws[lw_k16 + 0][lw_r16] = wv.x;
                ws[lw_k16 + 1][lw_r16] = wv.y;
                __syncthreads();
#pragma unroll
                for (int kk = 0; kk < 32; kk++) {
                    float w = ws[kk][col16];
                    float2 a2 = *(const float2*)&as[kk][bq16 << 1];
                    acc[0] += w * a2.x; acc[1] += w * a2.y;
                }
            }
            float bias = qb[qnb + col16];
#pragma unroll
            for (int i = 0; i < 2; i++)
                g_q[(size_t)(bq16 * 2 + i) * Hh + qnb + col16] = acc[i] + bias;
        }
        grid_bar(++ep);

        // ---- P2: scores[b][s] = kT[b,s,:] . q[b,:]  (768 warps over 8192 dots) ----
        {
            int gw = bid * 8 + warp;
            for (int d = gw; d < Bb * SEe; d += NBLK * 8) {
                int b = d >> 8, s = d & 255;
                const float4* qr = (const float4*)(g_q + (size_t)b * Hh);
                const float4* kr = (const float4*)(g_kT + ((size_t)b * SEe + s) * Hh);
                float a = 0.f;
#pragma unroll
                for (int i = 0; i < 8; i++) {
                    float4 qv = qr[lane + 32 * i];
                    float4 kv = kr[lane + 32 * i];
                    a += qv.x * kv.x + qv.y * kv.y + qv.z * kv.z + qv.w * kv.w;
                }
#pragma unroll
                for (int o = 16; o > 0; o >>= 1) a += __shfl_xor_sync(0xffffffffu, a, o);
                if (lane == 0) g_sc[d] = a;
            }
        }
        grid_bar(++ep);

        // ---- P3: softmax + ctx  (blocks 0..31, block = batch) ----
        if (bid < 32) {
            int b = bid;
            float v = g_sc[b * SEe + tid];
            float m = v;
#pragma unroll
            for (int o = 16; o > 0; o >>= 1) m = fmaxf(m, __shfl_xor_sync(0xffffffffu, m, o));
            if (lane == 0) red[warp] = m;
            __syncthreads();
            float mm = red[0];
#pragma unroll
            for (int i = 1; i < 8; i++) mm = fmaxf(mm, red[i]);
            float e = expf(v - mm);
            float ssum = e;
#pragma unroll
            for (int o = 16; o > 0; o >>= 1) ssum += __shfl_xor_sync(0xffffffffu, ssum, o);
            __syncthreads();
            if (lane == 0) red[warp] = ssum;
            __syncthreads();
            float tot = 0.f;
#pragma unroll
            for (int i = 0; i < 8; i++) tot += red[i];
            sc[tid] = e / tot;
            __syncthreads();

            float c0 = 0.f, c1 = 0.f, c2 = 0.f, c3 = 0.f;
#pragma unroll 4
            for (int s = 0; s < SEe; s++) {
                float a = sc[s];
                const float* er = g_enc_out + ((size_t)s * Bb + b) * Hh;
                c0 += a * er[tid];
                c1 += a * er[tid + 256];
                c2 += a * er[tid + 512];
                c3 += a * er[tid + 768];
            }
            float* cp = g_ctx + (size_t)b * Hh;
            cp[tid] = c0; cp[tid + 256] = c1; cp[tid + 512] = c2; cp[tid + 768] = c3;
        }
        grid_bar(++ep);

        // ---- P4: gh = h@Whh.T (blocks 0..47) ; gc = ctx@Wc.T (blocks 48..95) ----
        {
            const float* A;
            const float* Wp;
            float* outp;
            int ldw, cnb;
            if (bid < 48) { A = h;     Wp = Whh; ldw = Hh;      cnb = bid * 64;        outp = g_gh; }
            else          { A = g_ctx; Wp = Wc;  ldw = Ee + Hh; cnb = (bid - 48) * 64; outp = g_gc; }

            float acc0[4] = {0.f, 0.f, 0.f, 0.f};
            float acc1[4] = {0.f, 0.f, 0.f, 0.f};
            const float* ap = A + (size_t)la_b * Hh + la_k;
            const float* wp = Wp + (size_t)(cnb + lw_r64) * ldw + lw_k64;
            for (int k0 = 0; k0 < Hh; k0 += 32) {
                float4 av  = *(const float4*)(ap + k0);
                float4 wv0 = *(const float4*)(wp + k0);
                float4 wv1 = *(const float4*)(wp + k0 + 4);
                __syncthreads();
                as[la_k + 0][la_b] = av.x; as[la_k + 1][la_b] = av.y;
                as[la_k + 2][la_b] = av.z; as[la_k + 3][la_b] = av.w;
                ws[lw_k64 + 0][lw_r64] = wv0.x; ws[lw_k64 + 1][lw_r64] = wv0.y;
                ws[lw_k64 + 2][lw_r64] = wv0.z; ws[lw_k64 + 3][lw_r64] = wv0.w;
                ws[lw_k64 + 4][lw_r64] = wv1.x; ws[lw_k64 + 5][lw_r64] = wv1.y;
                ws[lw_k64 + 6][lw_r64] = wv1.z; ws[lw_k64 + 7][lw_r64] = wv1.w;
                __syncthreads();
#pragma unroll
                for (int kk = 0; kk < 32; kk++) {
                    float2 w2 = *(const float2*)&ws[kk][j2 << 1];
                    float4 a4 = *(const float4*)&as[kk][bg << 2];
                    acc0[0] += w2.x * a4.x; acc0[1] += w2.x * a4.y;
                    acc0[2] += w2.x * a4.z; acc0[3] += w2.x * a4.w;
                    acc1[0] += w2.y * a4.x; acc1[1] += w2.y * a4.y;
                    acc1[2] += w2.y * a4.z; acc1[3] += w2.y * a4.w;
                }
            }
            int n0 = cnb + (j2 << 1);
#pragma unroll
            for (int i = 0; i < 4; i++) {
                float2 v2; v2.x = acc0[i]; v2.y = acc1[i];
                *(float2*)&outp[(size_t)(bg * 4 + i) * G3 + n0] = v2;
            }
        }
        grid_bar(++ep);

        // ---- P5: gate + state update ----
        for (int idx = bid * 256 + tid; idx < Bb * Hh; idx += NBLK * 256) {
            int b = idx >> 10, j = idx & 1023;
            const float* gx = g_dec_gx + (size_t)(t * Bb + b) * G3;
            const float* gh = g_gh + (size_t)b * G3;
            const float* gc = g_gc + (size_t)b * G3;
            float gir = gx[j] + gc[j];
            float giz = gx[Hh + j] + gc[Hh + j];
            float gin = gx[2 * Hh + j] + gc[2 * Hh + j];
            float ghr = gh[j] + bhh[j];
            float ghz = gh[Hh + j] + bhh[Hh + j];
            float ghn = gh[2 * Hh + j] + bhh[2 * Hh + j];
            float r = sigf(gir + ghr);
            float z = sigf(giz + ghz);
            float n = tanhf(gin + r * ghn);
            float hold = h[idx];
            float h2 = (1.f - z) * n + z * hold;
            hn[idx] = h2;
            g_dec_out[(size_t)t * Bb * Hh + idx] = h2;
        }
        grid_bar(++ep);
    }
}

extern "C" void kernel_launch(void* const* d_in, const int* in_sizes, int n_in,
                              void* d_out, int out_size)
{
    const int*   enc_in   = (const int*)d_in[0];
    const int*   dec_in   = (const int*)d_in[1];
    const int*   enc_len  = (const int*)d_in[2];
    const float* emb      = (const float*)d_in[4];
    const float* enc_Wih  = (const float*)d_in[5];
    const float* enc_Whh  = (const float*)d_in[6];
    const float* enc_bih  = (const float*)d_in[7];
    const float* enc_bhh  = (const float*)d_in[8];
    const float* dec_Wih  = (const float*)d_in[9];
    const float* dec_Whh  = (const float*)d_in[10];
    const float* dec_bih  = (const float*)d_in[11];
    const float* dec_bhh  = (const float*)d_in[12];
    const float* attn_kW  = (const float*)d_in[13];
    const float* attn_kb  = (const float*)d_in[14];
    const float* attn_qW  = (const float*)d_in[15];
    const float* attn_qb  = (const float*)d_in[16];
    const float* logits_W = (const float*)d_in[17];
    const float* logits_b = (const float*)d_in[18];
    float* out = (float*)d_out;
    (void)in_sizes; (void)n_in; (void)out_size;

    float *p_enc_gi, *p_dec_gx, *p_enc_out, *p_kT, *p_dec_out;
    int *p_enc_rows, *p_dec_rows;
    cudaGetSymbolAddress((void**)&p_enc_gi,  g_enc_gi);
    cudaGetSymbolAddress((void**)&p_dec_gx,  g_dec_gx);
    cudaGetSymbolAddress((void**)&p_enc_out, g_enc_out);
    cudaGetSymbolAddress((void**)&p_kT,      g_kT);
    cudaGetSymbolAddress((void**)&p_dec_out, g_dec_out);
    cudaGetSymbolAddress((void**)&p_enc_rows, g_enc_rows);
    cudaGetSymbolAddress((void**)&p_dec_rows, g_dec_rows);

    build_rows_kernel<<<32, 256>>>(enc_in, dec_in);
    init_h_kernel<<<(Bb * Hh) / 256, 256>>>();

    // hoisted input projections (embedding gather fused)
    gemm_nt<<<dim3(G3 / 128, (SEe * Bb) / 128), 256>>>(
        emb, p_enc_rows, Ee, enc_Wih, Ee, enc_bih, p_enc_gi, G3, Ee, 0);
    gemm_nt<<<dim3(G3 / 128, (SDd * Bb) / 128), 256>>>(
        emb, p_dec_rows, Ee, dec_Wih, Ee + Hh, dec_bih, p_dec_gx, G3, Ee, 0);

    // encoder: 256 steps, one persistent launch (final state lands in g_h0)
    enc_persistent<<<NBLK, 256>>>(enc_Whh, enc_bhh, enc_len);

    // attention keys: (t,b,h) -> (b,s,h) via Sremap=SE
    gemm_nt<<<dim3(Hh / 128, (SEe * Bb) / 128), 256>>>(
        p_enc_out, nullptr, Hh, attn_kW, Hh, attn_kb, p_kT, Hh, Hh, SEe);

    // decoder: 128 steps, one persistent launch
    dec_persistent<<<NBLK, 256>>>(attn_qW, attn_qb, dec_Whh, dec_Wih, dec_bhh);

    // logits: (t,b,h) @ W.T -> out[b*SD+t][v]  via Sremap=SD
    gemm_nt<<<dim3(Vv / 128, (SDd * Bb) / 128), 256>>>(
        p_dec_out, nullptr, Hh, logits_W, Hh, logits_b, out, Vv, Hh, SDd);
}

// round 6
// speedup vs baseline: 1.5353x; 1.5353x over previous
#include <cuda_runtime.h>
#include <cstdint>
#include <cstddef>

#define Vv   32000
#define Ee   1024
#define Hh   1024
#define Bb   32
#define SEe  256
#define SDd  128
#define G3   3072
#define NBLK 96

__device__ float g_enc_gi[(size_t)SEe * Bb * G3];
__device__ float g_dec_gx[(size_t)SDd * Bb * G3];
__device__ float g_enc_out[(size_t)SEe * Bb * Hh];
__device__ float g_kT[(size_t)Bb * SEe * Hh];
__device__ float g_dec_out[(size_t)SDd * Bb * Hh];
__device__ float g_h0[Bb * Hh];
__device__ float g_h1[Bb * Hh];
__device__ float g_ctx[Bb * Hh];
__device__ float g_q[Bb * Hh];
__device__ float g_sc[Bb * SEe];
__device__ float g_gh[Bb * G3];
__device__ float g_gc[Bb * G3];
__device__ int   g_enc_rows[SEe * Bb];
__device__ int   g_dec_rows[SDd * Bb];
__device__ unsigned g_bar_count;
__device__ unsigned g_bar_sense;

__device__ __forceinline__ float sigf(float x) { return 1.f / (1.f + expf(-x)); }

// software grid barrier: all NBLK blocks co-resident (NBLK <= 148 SMs, wave-1)
__device__ __forceinline__ void grid_bar(unsigned target)
{
    __syncthreads();
    if (threadIdx.x == 0) {
        __threadfence();
        if (atomicAdd(&g_bar_count, 1u) == NBLK - 1) {
            atomicExch(&g_bar_count, 0u);
            __threadfence();
            atomicExch(&g_bar_sense, target);
        } else {
            while (*(volatile unsigned*)&g_bar_sense < target) __nanosleep(64);
            __threadfence();
        }
    }
    __syncthreads();
}

__global__ void __launch_bounds__(256) build_rows_kernel(
    const int* __restrict__ enc_in, const int* __restrict__ dec_in)
{
    int m = blockIdx.x * 256 + threadIdx.x;
    if (m < SEe * Bb) {
        int t = m >> 5, b = m & 31;
        g_enc_rows[m] = enc_in[b * SEe + t];
    }
    if (m < SDd * Bb) {
        int t = m >> 5, b = m & 31;
        g_dec_rows[m] = dec_in[b * SDd + t];
    }
}

__global__ void __launch_bounds__(256) init_h_kernel()
{
    int i = blockIdx.x * 256 + threadIdx.x;
    if (i < Bb * Hh) g_h0[i] = 0.f;
}

// big-GEMM: C[remap(m)][n] = bias[n] + sum_k A[arows?arows[m]:m][k] * W[n][k]
__global__ void __launch_bounds__(256) gemm_nt(
    const float* __restrict__ A, const int* __restrict__ arows, int lda,
    const float* __restrict__ W, int ldw,
    const float* __restrict__ bias,
    float* __restrict__ C, int N, int K, int Sremap)
{
    __shared__ __align__(16) float As[16][132];
    __shared__ __align__(16) float Bs[16][132];
    int tid = threadIdx.x;
    int bm = blockIdx.y * 128, bn = blockIdx.x * 128;

    int lr = tid >> 2;
    int lk = (tid & 3) << 2;

    int r0 = bm + lr, r1 = bm + lr + 64;
    int ar0 = arows ? arows[r0] : r0;
    int ar1 = arows ? arows[r1] : r1;
    const float* arow0 = A + (size_t)ar0 * lda;
    const float* arow1 = A + (size_t)ar1 * lda;
    const float* wrow0 = W + (size_t)(bn + lr) * ldw;
    const float* wrow1 = W + (size_t)(bn + lr + 64) * ldw;

    int ty = tid >> 4;
    int tx = tid & 15;

    float acc[8][8];
#pragma unroll
    for (int i = 0; i < 8; i++)
#pragma unroll
        for (int j = 0; j < 8; j++) acc[i][j] = 0.f;

    for (int k0 = 0; k0 < K; k0 += 16) {
        float4 a0 = *(const float4*)(arow0 + k0 + lk);
        float4 a1 = *(const float4*)(arow1 + k0 + lk);
        float4 b0 = *(const float4*)(wrow0 + k0 + lk);
        float4 b1 = *(const float4*)(wrow1 + k0 + lk);
        __syncthreads();
        As[lk + 0][lr] = a0.x; As[lk + 1][lr] = a0.y; As[lk + 2][lr] = a0.z; As[lk + 3][lr] = a0.w;
        As[lk + 0][lr + 64] = a1.x; As[lk + 1][lr + 64] = a1.y; As[lk + 2][lr + 64] = a1.z; As[lk + 3][lr + 64] = a1.w;
        Bs[lk + 0][lr] = b0.x; Bs[lk + 1][lr] = b0.y; Bs[lk + 2][lr] = b0.z; Bs[lk + 3][lr] = b0.w;
        Bs[lk + 0][lr + 64] = b1.x; Bs[lk + 1][lr + 64] = b1.y; Bs[lk + 2][lr + 64] = b1.z; Bs[lk + 3][lr + 64] = b1.w;
        __syncthreads();
#pragma unroll
        for (int kk = 0; kk < 16; kk++) {
            float a[8], b[8];
            *(float4*)(a)     = *(const float4*)&As[kk][ty * 8];
            *(float4*)(a + 4) = *(const float4*)&As[kk][ty * 8 + 4];
            *(float4*)(b)     = *(const float4*)&Bs[kk][tx * 8];
            *(float4*)(b + 4) = *(const float4*)&Bs[kk][tx * 8 + 4];
#pragma unroll
            for (int i = 0; i < 8; i++)
#pragma unroll
                for (int j = 0; j < 8; j++) acc[i][j] += a[i] * b[j];
        }
    }

    int nbase = bn + tx * 8;
    float bj[8];
#pragma unroll
    for (int j = 0; j < 8; j++) bj[j] = bias ? bias[nbase + j] : 0.f;

#pragma unroll
    for (int i = 0; i < 8; i++) {
        int m = bm + ty * 8 + i;
        size_t orow = (Sremap > 0) ? ((size_t)(m & 31) * Sremap + (size_t)(m >> 5)) : (size_t)m;
        float* cp = C + orow * (size_t)N + nbase;
        float v[8];
#pragma unroll
        for (int j = 0; j < 8; j++) v[j] = acc[i][j] + bj[j];
        *(float4*)(cp)     = *(float4*)(v);
        *(float4*)(cp + 4) = *(float4*)(v + 4);
    }
}

// ---------------- skinny GEMM: out[b][cb+n] = (bias) + sum_k A[b][k]*W[cb+n][k]
// 32 batches x 32 cols per block, K=1024, 256 threads, 2x2 microtile,
// 64-deep K chunks with register prefetch. A row stride = Hh.
__device__ __forceinline__ void skinny32(
    const float* __restrict__ A,
    const float* __restrict__ W, int ldw, int cb,
    const float* __restrict__ bias,
    float* __restrict__ outp, int oldd,
    float (*as)[34], float (*ws)[34])
{
    int tid = threadIdx.x;
    int r0  = tid >> 4;           // 0..15 (load row)
    int kq4 = (tid & 15) << 2;    // 0..60 (load k)
    int bg2 = (tid >> 4) << 1;    // output batch base
    int cg2 = (tid & 15) << 1;    // output col base

    const float* Ar0 = A + (size_t)r0 * Hh + kq4;
    const float* Ar1 = Ar0 + (size_t)16 * Hh;
    const float* Wr0 = W + (size_t)(cb + r0) * ldw + kq4;
    const float* Wr1 = Wr0 + (size_t)16 * ldw;

    float4 a0 = *(const float4*)Ar0;
    float4 a1 = *(const float4*)Ar1;
    float4 w0 = *(const float4*)Wr0;
    float4 w1 = *(const float4*)Wr1;

    float acc00 = 0.f, acc01 = 0.f, acc10 = 0.f, acc11 = 0.f;

    for (int k0 = 0; k0 < Hh; k0 += 64) {
        __syncthreads();
        as[kq4 + 0][r0] = a0.x; as[kq4 + 1][r0] = a0.y; as[kq4 + 2][r0] = a0.z; as[kq4 + 3][r0] = a0.w;
        as[kq4 + 0][r0 + 16] = a1.x; as[kq4 + 1][r0 + 16] = a1.y; as[kq4 + 2][r0 + 16] = a1.z; as[kq4 + 3][r0 + 16] = a1.w;
        ws[kq4 + 0][r0] = w0.x; ws[kq4 + 1][r0] = w0.y; ws[kq4 + 2][r0] = w0.z; ws[kq4 + 3][r0] = w0.w;
        ws[kq4 + 0][r0 + 16] = w1.x; ws[kq4 + 1][r0 + 16] = w1.y; ws[kq4 + 2][r0 + 16] = w1.z; ws[kq4 + 3][r0 + 16] = w1.w;
        __syncthreads();
        if (k0 + 64 < Hh) {
            a0 = *(const float4*)(Ar0 + k0 + 64);
            a1 = *(const float4*)(Ar1 + k0 + 64);
            w0 = *(const float4*)(Wr0 + k0 + 64);
            w1 = *(const float4*)(Wr1 + k0 + 64);
        }
#pragma unroll 32
        for (int kk = 0; kk < 64; kk++) {
            float2 a2 = *(const float2*)&as[kk][bg2];
            float2 w2 = *(const float2*)&ws[kk][cg2];
            acc00 += a2.x * w2.x; acc01 += a2.x * w2.y;
            acc10 += a2.y * w2.x; acc11 += a2.y * w2.y;
        }
    }

    float bv0 = bias ? bias[cb + cg2]     : 0.f;
    float bv1 = bias ? bias[cb + cg2 + 1] : 0.f;
    float* o0 = outp + (size_t)bg2 * oldd + cb + cg2;
    float* o1 = o0 + oldd;
    o0[0] = acc00 + bv0; o0[1] = acc01 + bv1;
    o1[0] = acc10 + bv0; o1[1] = acc11 + bv1;
}

// ---------------- persistent encoder ----------------
__global__ void __launch_bounds__(256) enc_persistent(
    const float* __restrict__ Whh, const float* __restrict__ bhh,
    const int* __restrict__ enclen)
{
    __shared__ unsigned s_base;
    __shared__ __align__(16) float as[64][34];
    __shared__ __align__(16) float ws[64][34];
    int tid = threadIdx.x, bid = blockIdx.x;
    if (tid == 0) s_base = *(volatile unsigned*)&g_bar_sense;
    __syncthreads();
    unsigned ep = s_base;

    for (int t = 0; t < SEe; t++) {
        const float* h  = (t & 1) ? g_h1 : g_h0;
        float*       hn = (t & 1) ? g_h0 : g_h1;

        // phase A: gh = h @ Whh.T   (96 blocks x 32 cols = 3072)
        skinny32(h, Whh, Hh, bid * 32, nullptr, g_gh, G3, as, ws);
        grid_bar(++ep);

        // phase B: gate + state update + masked output
        for (int idx = bid * 256 + tid; idx < Bb * Hh; idx += NBLK * 256) {
            int b = idx >> 10, j = idx & 1023;
            const float* gi = g_enc_gi + (size_t)(t * Bb + b) * G3;
            const float* gh = g_gh + (size_t)b * G3;
            float r = sigf(gi[j]          + gh[j]          + bhh[j]);
            float z = sigf(gi[Hh + j]     + gh[Hh + j]     + bhh[Hh + j]);
            float n = tanhf(gi[2 * Hh + j] + r * (gh[2 * Hh + j] + bhh[2 * Hh + j]));
            float hold = h[idx];
            float hnv = (1.f - z) * n + z * hold;
            bool msk = t < enclen[b];
            hn[idx] = msk ? hnv : hold;
            g_enc_out[(size_t)t * Bb * Hh + idx] = msk ? hnv : 0.f;
        }
        grid_bar(++ep);
    }
}

// ---------------- persistent decoder ----------------
__global__ void __launch_bounds__(256) dec_persistent(
    const float* __restrict__ qW, const float* __restrict__ qb,
    const float* __restrict__ Whh, const float* __restrict__ Wih,
    const float* __restrict__ bhh)
{
    __shared__ unsigned s_base;
    __shared__ __align__(16) float as[64][34];
    __shared__ __align__(16) float ws[64][34];
    __shared__ float sc[SEe];
    __shared__ float red[8];
    int tid = threadIdx.x, bid = blockIdx.x, lane = tid & 31, warp = tid >> 5;
    if (tid == 0) s_base = *(volatile unsigned*)&g_bar_sense;
    __syncthreads();
    unsigned ep = s_base;

    const float* Wc = Wih + Ee;   // ctx columns of dec_Wih, row length Ee+Hh

    for (int t = 0; t < SDd; t++) {
        const float* h  = (t & 1) ? g_h1 : g_h0;
        float*       hn = (t & 1) ? g_h0 : g_h1;

        // A1: q (blocks 0..31) || gh cols 0..2047 (blocks 32..95)
        if (bid < 32)
            skinny32(h, qW, Hh, bid * 32, qb, g_q, Hh, as, ws);
        else
            skinny32(h, Whh, Hh, (bid - 32) * 32, nullptr, g_gh, G3, as, ws);
        grid_bar(++ep);

        // A2: scores[b][s] = kT[b,s,:] . q[b,:]
        for (int d = bid * 8 + warp; d < Bb * SEe; d += NBLK * 8) {
            int b = d >> 8, s = d & 255;
            const float4* qr = (const float4*)(g_q + (size_t)b * Hh);
            const float4* kr = (const float4*)(g_kT + ((size_t)b * SEe + s) * Hh);
            float a = 0.f;
#pragma unroll
            for (int i = 0; i < 8; i++) {
                float4 qv = qr[lane + 32 * i];
                float4 kv = kr[lane + 32 * i];
                a += qv.x * kv.x + qv.y * kv.y + qv.z * kv.z + qv.w * kv.w;
            }
#pragma unroll
            for (int o = 16; o > 0; o >>= 1) a += __shfl_xor_sync(0xffffffffu, a, o);
            if (lane == 0) g_sc[d] = a;
        }
        grid_bar(++ep);

        // A3: redundant softmax + ctx halves (blocks 0..63) || gh tail (64..95)
        if (bid < 64) {
            int b = bid >> 1, half = bid & 1;
            float v = g_sc[b * SEe + tid];
            float m = v;
#pragma unroll
            for (int o = 16; o > 0; o >>= 1) m = fmaxf(m, __shfl_xor_sync(0xffffffffu, m, o));
            if (lane == 0) red[warp] = m;
            __syncthreads();
            float mm = red[0];
#pragma unroll
            for (int i = 1; i < 8; i++) mm = fmaxf(mm, red[i]);
            float e = expf(v - mm);
            float ssum = e;
#pragma unroll
            for (int o = 16; o > 0; o >>= 1) ssum += __shfl_xor_sync(0xffffffffu, ssum, o);
            __syncthreads();
            if (lane == 0) red[warp] = ssum;
            __syncthreads();
            float tot = 0.f;
#pragma unroll
            for (int i = 0; i < 8; i++) tot += red[i];
            sc[tid] = e / tot;
            __syncthreads();

            int c0 = half * 512 + tid;
            float s0 = 0.f, s1 = 0.f;
#pragma unroll 4
            for (int s = 0; s < SEe; s++) {
                float a = sc[s];
                const float* er = g_enc_out + ((size_t)s * Bb + b) * Hh;
                s0 += a * er[c0];
                s1 += a * er[c0 + 256];
            }
            g_ctx[(size_t)b * Hh + c0]       = s0;
            g_ctx[(size_t)b * Hh + c0 + 256] = s1;
        } else {
            skinny32(h, Whh, Hh, 2048 + (bid - 64) * 32, nullptr, g_gh, G3, as, ws);
        }
        grid_bar(++ep);

        // A4: gc = ctx @ Wc.T  (96 blocks x 32 cols)
        skinny32(g_ctx, Wc, Ee + Hh, bid * 32, nullptr, g_gc, G3, as, ws);
        grid_bar(++ep);

        // A5: gate + state update
        for (int idx = bid * 256 + tid; idx < Bb * Hh; idx += NBLK * 256) {
            int b = idx >> 10, j = idx & 1023;
            const float* gx = g_dec_gx + (size_t)(t * Bb + b) * G3;
            const float* gh = g_gh + (size_t)b * G3;
            const float* gc = g_gc + (size_t)b * G3;
            float r = sigf(gx[j]          + gc[j]          + gh[j]          + bhh[j]);
            float z = sigf(gx[Hh + j]     + gc[Hh + j]     + gh[Hh + j]     + bhh[Hh + j]);
            float n = tanhf(gx[2 * Hh + j] + gc[2 * Hh + j] + r * (gh[2 * Hh + j] + bhh[2 * Hh + j]));
            float hold = h[idx];
            float h2 = (1.f - z) * n + z * hold;
            hn[idx] = h2;
            g_dec_out[(size_t)t * Bb * Hh + idx] = h2;
        }
        grid_bar(++ep);
    }
}

extern "C" void kernel_launch(void* const* d_in, const int* in_sizes, int n_in,
                              void* d_out, int out_size)
{
    const int*   enc_in   = (const int*)d_in[0];
    const int*   dec_in   = (const int*)d_in[1];
    const int*   enc_len  = (const int*)d_in[2];
    const float* emb      = (const float*)d_in[4];
    const float* enc_Wih  = (const float*)d_in[5];
    const float* enc_Whh  = (const float*)d_in[6];
    const float* enc_bih  = (const float*)d_in[7];
    const float* enc_bhh  = (const float*)d_in[8];
    const float* dec_Wih  = (const float*)d_in[9];
    const float* dec_Whh  = (const float*)d_in[10];
    const float* dec_bih  = (const float*)d_in[11];
    const float* dec_bhh  = (const float*)d_in[12];
    const float* attn_kW  = (const float*)d_in[13];
    const float* attn_kb  = (const float*)d_in[14];
    const float* attn_qW  = (const float*)d_in[15];
    const float* attn_qb  = (const float*)d_in[16];
    const float* logits_W = (const float*)d_in[17];
    const float* logits_b = (const float*)d_in[18];
    float* out = (float*)d_out;
    (void)in_sizes; (void)n_in; (void)out_size;

    float *p_enc_gi, *p_dec_gx, *p_enc_out, *p_kT, *p_dec_out;
    int *p_enc_rows, *p_dec_rows;
    cudaGetSymbolAddress((void**)&p_enc_gi,  g_enc_gi);
    cudaGetSymbolAddress((void**)&p_dec_gx,  g_dec_gx);
    cudaGetSymbolAddress((void**)&p_enc_out, g_enc_out);
    cudaGetSymbolAddress((void**)&p_kT,      g_kT);
    cudaGetSymbolAddress((void**)&p_dec_out, g_dec_out);
    cudaGetSymbolAddress((void**)&p_enc_rows, g_enc_rows);
    cudaGetSymbolAddress((void**)&p_dec_rows, g_dec_rows);

    build_rows_kernel<<<32, 256>>>(enc_in, dec_in);
    init_h_kernel<<<(Bb * Hh) / 256, 256>>>();

    // hoisted input projections (embedding gather fused)
    gemm_nt<<<dim3(G3 / 128, (SEe * Bb) / 128), 256>>>(
        emb, p_enc_rows, Ee, enc_Wih, Ee, enc_bih, p_enc_gi, G3, Ee, 0);
    gemm_nt<<<dim3(G3 / 128, (SDd * Bb) / 128), 256>>>(
        emb, p_dec_rows, Ee, dec_Wih, Ee + Hh, dec_bih, p_dec_gx, G3, Ee, 0);

    // encoder: 256 steps, one persistent launch (final state lands in g_h0)
    enc_persistent<<<NBLK, 256>>>(enc_Whh, enc_bhh, enc_len);

    // attention keys: (t,b,h) -> (b,s,h) via Sremap=SE
    gemm_nt<<<dim3(Hh / 128, (SEe * Bb) / 128), 256>>>(
        p_enc_out, nullptr, Hh, attn_kW, Hh, attn_kb, p_kT, Hh, Hh, SEe);

    // decoder: 128 steps, one persistent launch
    dec_persistent<<<NBLK, 256>>>(attn_qW, attn_qb, dec_Whh, dec_Wih, dec_bhh);

    // logits: (t,b,h) @ W.T -> out[b*SD+t][v]  via Sremap=SD
    gemm_nt<<<dim3(Vv / 128, (SDd * Bb) / 128), 256>>>(
        p_dec_out, nullptr, Hh, logits_W, Hh, logits_b, out, Vv, Hh, SDd);
}

// round 7
// speedup vs baseline: 2.0197x; 1.3155x over previous
#include <cuda_runtime.h>
#include <cstdint>
#include <cstddef>

#define Vv   32000
#define Ee   1024
#define Hh   1024
#define Bb   32
#define SEe  256
#define SDd  128
#define G3   3072
#define NBLK 96

__device__ float g_enc_gi[(size_t)SEe * Bb * G3];
__device__ float g_dec_gx[(size_t)SDd * Bb * G3];
__device__ float g_enc_out[(size_t)SEe * Bb * Hh];
__device__ float g_kT[(size_t)Bb * SEe * Hh];
__device__ float g_dec_out[(size_t)SDd * Bb * Hh];
__device__ float g_h0[Bb * Hh];
__device__ float g_h1[Bb * Hh];
__device__ float g_ctx[Bb * Hh];
__device__ float g_sc[Bb * SEe];
__device__ float g_qp[2 * (size_t)Bb * Hh];
__device__ float g_ghp[2 * (size_t)Bb * G3];
__device__ float g_gcp[2 * (size_t)Bb * G3];
__device__ int   g_enc_rows[SEe * Bb];
__device__ int   g_dec_rows[SDd * Bb];
__device__ unsigned g_bar_count;
__device__ unsigned g_bar_sense;

__device__ __forceinline__ float sigf(float x) { return 1.f / (1.f + expf(-x)); }

__device__ __forceinline__ void grid_bar(unsigned target)
{
    __syncthreads();
    if (threadIdx.x == 0) {
        __threadfence();
        if (atomicAdd(&g_bar_count, 1u) == NBLK - 1) {
            atomicExch(&g_bar_count, 0u);
            __threadfence();
            atomicExch(&g_bar_sense, target);
        } else {
            while (*(volatile unsigned*)&g_bar_sense < target) __nanosleep(64);
            __threadfence();
        }
    }
    __syncthreads();
}

__global__ void __launch_bounds__(256) build_rows_kernel(
    const int* __restrict__ enc_in, const int* __restrict__ dec_in)
{
    int m = blockIdx.x * 256 + threadIdx.x;
    if (m < SEe * Bb) {
        int t = m >> 5, b = m & 31;
        g_enc_rows[m] = enc_in[b * SEe + t];
    }
    if (m < SDd * Bb) {
        int t = m >> 5, b = m & 31;
        g_dec_rows[m] = dec_in[b * SDd + t];
    }
}

__global__ void __launch_bounds__(256) init_h_kernel()
{
    int i = blockIdx.x * 256 + threadIdx.x;
    if (i < Bb * Hh) g_h0[i] = 0.f;
}

// ================= tf32 tensor-core GEMM =================
__device__ __forceinline__ float to_tf32(float x)
{
    uint32_t u;
    asm("cvt.rna.tf32.f32 %0, %1;" : "=r"(u) : "f"(x));
    return __uint_as_float(u);
}

__device__ __forceinline__ float4 cvt4(float4 v)
{
    float4 r;
    r.x = to_tf32(v.x); r.y = to_tf32(v.y); r.z = to_tf32(v.z); r.w = to_tf32(v.w);
    return r;
}

__device__ __forceinline__ void mma_tf32(float* c, const float* a, const float* b)
{
    asm volatile(
        "mma.sync.aligned.m16n8k8.row.col.f32.tf32.tf32.f32 "
        "{%0,%1,%2,%3}, {%4,%5,%6,%7}, {%8,%9}, {%0,%1,%2,%3};"
        : "+f"(c[0]), "+f"(c[1]), "+f"(c[2]), "+f"(c[3])
        : "r"(__float_as_uint(a[0])), "r"(__float_as_uint(a[1])),
          "r"(__float_as_uint(a[2])), "r"(__float_as_uint(a[3])),
          "r"(__float_as_uint(b[0])), "r"(__float_as_uint(b[1])));
}

// C[remap(m)][n] = bias[n] + sum_k A[arows?arows[m]:m][k] * W[n][k]
// BM=BN=128, BK=16, 256 threads (8 warps 4x2, warp tile 32x64), tf32 mma.
__global__ void __launch_bounds__(256) gemm_tf32(
    const float* __restrict__ A, const int* __restrict__ arows, int lda,
    const float* __restrict__ W, int ldw,
    const float* __restrict__ bias,
    float* __restrict__ C, int N, int K, int Sremap)
{
    __shared__ __align__(16) float As[2][128][20];
    __shared__ __align__(16) float Bs[2][128][20];

    int tid = threadIdx.x;
    int bm = blockIdx.y * 128, bn = blockIdx.x * 128;
    int lr = tid >> 2;
    int lk = (tid & 3) << 2;

    int ar0 = arows ? arows[bm + lr] : bm + lr;
    int ar1 = arows ? arows[bm + lr + 64] : bm + lr + 64;
    const float* arow0 = A + (size_t)ar0 * lda + lk;
    const float* arow1 = A + (size_t)ar1 * lda + lk;
    const float* wrow0 = W + (size_t)(bn + lr) * ldw + lk;
    const float* wrow1 = W + (size_t)(bn + lr + 64) * ldw + lk;

    int warp = tid >> 5, lane = tid & 31;
    int wm = (warp >> 1) * 32, wn = (warp & 1) * 64;
    int g = lane >> 2, tg = lane & 3;

    float acc[2][8][4];
#pragma unroll
    for (int mt = 0; mt < 2; mt++)
#pragma unroll
        for (int nt = 0; nt < 8; nt++)
#pragma unroll
            for (int i = 0; i < 4; i++) acc[mt][nt][i] = 0.f;

    float4 a0 = *(const float4*)arow0;
    float4 a1 = *(const float4*)arow1;
    float4 b0 = *(const float4*)wrow0;
    float4 b1 = *(const float4*)wrow1;

    int buf = 0;
    for (int k0 = 0; k0 < K; k0 += 16) {
        *(float4*)&As[buf][lr][lk]      = cvt4(a0);
        *(float4*)&As[buf][lr + 64][lk] = cvt4(a1);
        *(float4*)&Bs[buf][lr][lk]      = cvt4(b0);
        *(float4*)&Bs[buf][lr + 64][lk] = cvt4(b1);
        __syncthreads();
        if (k0 + 16 < K) {
            a0 = *(const float4*)(arow0 + k0 + 16);
            a1 = *(const float4*)(arow1 + k0 + 16);
            b0 = *(const float4*)(wrow0 + k0 + 16);
            b1 = *(const float4*)(wrow1 + k0 + 16);
        }
#pragma unroll
        for (int ks = 0; ks < 2; ks++) {
            float af[2][4], bf[8][2];
#pragma unroll
            for (int mt = 0; mt < 2; mt++) {
                const float* p0 = &As[buf][wm + mt * 16 + g][ks * 8 + tg];
                const float* p1 = &As[buf][wm + mt * 16 + g + 8][ks * 8 + tg];
                af[mt][0] = p0[0]; af[mt][1] = p1[0];
                af[mt][2] = p0[4]; af[mt][3] = p1[4];
            }
#pragma unroll
            for (int nt = 0; nt < 8; nt++) {
                const float* p = &Bs[buf][wn + nt * 8 + g][ks * 8 + tg];
                bf[nt][0] = p[0]; bf[nt][1] = p[4];
            }
#pragma unroll
            for (int mt = 0; mt < 2; mt++)
#pragma unroll
                for (int nt = 0; nt < 8; nt++)
                    mma_tf32(acc[mt][nt], af[mt], bf[nt]);
        }
        buf ^= 1;
    }

#pragma unroll
    for (int mt = 0; mt < 2; mt++) {
        int m0 = bm + wm + mt * 16 + g;
#pragma unroll
        for (int half = 0; half < 2; half++) {
            int m = m0 + half * 8;
            size_t orow = (Sremap > 0) ? ((size_t)(m & 31) * Sremap + (size_t)(m >> 5)) : (size_t)m;
            float* crow = C + orow * (size_t)N;
#pragma unroll
            for (int nt = 0; nt < 8; nt++) {
                int col = bn + wn + nt * 8 + tg * 2;
                float bv0 = bias ? bias[col]     : 0.f;
                float bv1 = bias ? bias[col + 1] : 0.f;
                float2 v;
                v.x = acc[mt][nt][half * 2 + 0] + bv0;
                v.y = acc[mt][nt][half * 2 + 1] + bv1;
                *(float2*)&crow[col] = v;
            }
        }
    }
}

// ================= skinny GEMM partial (recurrent steps) =================
// out[b][cb+c] (partial over K slice [kbase, kbase+512)) = sum A[b][k]*W[cb+c][k]
// 32 batches x 64 cols per block, 256 threads, 2x4 microtile, FMA-bound.
__device__ __forceinline__ void skinny64(
    const float* __restrict__ A,
    const float* __restrict__ W, int ldw,
    int cb, int kbase,
    float* __restrict__ outp, int oldd,
    float (*as)[68], float (*ws)[68])
{
    const int tid = threadIdx.x;
    const int ar = tid >> 3;            // A row 0..31
    const int ak = (tid & 7) << 3;      // A k 0..56
    const int wr = tid >> 2;            // W row (out col) 0..63
    const int wk = (tid & 3) << 4;      // W k 0,16,32,48
    const int wrx = wr ^ ((wk >> 1) & 24);  // swizzled store column
    const int ob = (tid >> 4) << 1;     // out batch base
    const int oc = (tid & 15) << 2;     // out col base

    const float* Ap = A + (size_t)ar * Hh + kbase + ak;
    const float* Wp = W + (size_t)(cb + wr) * ldw + kbase + wk;

    float4 a0 = *(const float4*)Ap;
    float4 a1 = *(const float4*)(Ap + 4);
    float4 w0 = *(const float4*)Wp;
    float4 w1 = *(const float4*)(Wp + 4);
    float4 w2 = *(const float4*)(Wp + 8);
    float4 w3 = *(const float4*)(Wp + 12);

    float acc0[4] = {0.f, 0.f, 0.f, 0.f};
    float acc1[4] = {0.f, 0.f, 0.f, 0.f};

    for (int k0 = 0; k0 < 512; k0 += 64) {
        __syncthreads();
        *(float4*)&as[ar][ak]     = a0;
        *(float4*)&as[ar][ak + 4] = a1;
        ws[wk +  0][wrx] = w0.x; ws[wk +  1][wrx] = w0.y; ws[wk +  2][wrx] = w0.z; ws[wk +  3][wrx] = w0.w;
        ws[wk +  4][wrx] = w1.x; ws[wk +  5][wrx] = w1.y; ws[wk +  6][wrx] = w1.z; ws[wk +  7][wrx] = w1.w;
        ws[wk +  8][wrx] = w2.x; ws[wk +  9][wrx] = w2.y; ws[wk + 10][wrx] = w2.z; ws[wk + 11][wrx] = w2.w;
        ws[wk + 12][wrx] = w3.x; ws[wk + 13][wrx] = w3.y; ws[wk + 14][wrx] = w3.z; ws[wk + 15][wrx] = w3.w;
        __syncthreads();
        if (k0 + 64 < 512) {
            a0 = *(const float4*)(Ap + k0 + 64);
            a1 = *(const float4*)(Ap + k0 + 68);
            w0 = *(const float4*)(Wp + k0 + 64);
            w1 = *(const float4*)(Wp + k0 + 68);
            w2 = *(const float4*)(Wp + k0 + 72);
            w3 = *(const float4*)(Wp + k0 + 76);
        }
#pragma unroll 16
        for (int kk = 0; kk < 64; kk++) {
            float4 w4 = *(const float4*)&ws[kk][oc ^ ((kk >> 1) & 24)];
            float aa = as[ob][kk];
            float ab = as[ob + 1][kk];
            acc0[0] += aa * w4.x; acc0[1] += aa * w4.y; acc0[2] += aa * w4.z; acc0[3] += aa * w4.w;
            acc1[0] += ab * w4.x; acc1[1] += ab * w4.y; acc1[2] += ab * w4.z; acc1[3] += ab * w4.w;
        }
    }

    float* o0 = outp + (size_t)ob * oldd + cb + oc;
    *(float4*)o0 = make_float4(acc0[0], acc0[1], acc0[2], acc0[3]);
    *(float4*)(o0 + oldd) = make_float4(acc1[0], acc1[1], acc1[2], acc1[3]);
}

// ================= persistent encoder =================
__global__ void __launch_bounds__(256) enc_persistent(
    const float* __restrict__ Whh, const float* __restrict__ bhh,
    const int* __restrict__ enclen)
{
    __shared__ unsigned s_base;
    __shared__ __align__(16) float as[32][68];
    __shared__ __align__(16) float ws[64][68];
    int tid = threadIdx.x, bid = blockIdx.x;
    if (tid == 0) s_base = *(volatile unsigned*)&g_bar_sense;
    __syncthreads();
    unsigned ep = s_base;

    for (int t = 0; t < SEe; t++) {
        const float* h  = (t & 1) ? g_h1 : g_h0;
        float*       hn = (t & 1) ? g_h0 : g_h1;

        // phase A: gh partials (48 colgroups x 2 K-slices)
        skinny64(h, Whh, Hh, (bid >> 1) * 64, (bid & 1) * 512,
                 g_ghp + (size_t)(bid & 1) * (Bb * G3), G3, as, ws);
        grid_bar(++ep);

        // phase B: gate + state update + masked output
        for (int idx = bid * 256 + tid; idx < Bb * Hh; idx += NBLK * 256) {
            int b = idx >> 10, j = idx & 1023;
            const float* gi  = g_enc_gi + (size_t)(t * Bb + b) * G3;
            const float* gh0 = g_ghp + (size_t)b * G3;
            const float* gh1 = g_ghp + (size_t)(Bb * G3) + (size_t)b * G3;
            float hr = gh0[j]          + gh1[j]          + bhh[j];
            float hz = gh0[Hh + j]     + gh1[Hh + j]     + bhh[Hh + j];
            float hv = gh0[2*Hh + j]   + gh1[2*Hh + j]   + bhh[2*Hh + j];
            float r = sigf(gi[j] + hr);
            float z = sigf(gi[Hh + j] + hz);
            float n = tanhf(gi[2*Hh + j] + r * hv);
            float hold = h[idx];
            float hnv = (1.f - z) * n + z * hold;
            bool msk = t < enclen[b];
            hn[idx] = msk ? hnv : hold;
            g_enc_out[(size_t)t * Bb * Hh + idx] = msk ? hnv : 0.f;
        }
        grid_bar(++ep);
    }
}

// ================= persistent decoder =================
__global__ void __launch_bounds__(256) dec_persistent(
    const float* __restrict__ qW, const float* __restrict__ qb,
    const float* __restrict__ Whh, const float* __restrict__ Wih,
    const float* __restrict__ bhh)
{
    __shared__ unsigned s_base;
    __shared__ __align__(16) float as[32][68];
    __shared__ __align__(16) float ws[64][68];
    __shared__ __align__(16) float qs[Hh];
    __shared__ float sc[SEe];
    __shared__ float red[8];
    int tid = threadIdx.x, bid = blockIdx.x, lane = tid & 31, warp = tid >> 5;
    if (tid == 0) s_base = *(volatile unsigned*)&g_bar_sense;
    __syncthreads();
    unsigned ep = s_base;

    const float* Wc = Wih + Ee;   // ctx columns of dec_Wih, row stride Ee+Hh

    for (int t = 0; t < SDd; t++) {
        const float* h  = (t & 1) ? g_h1 : g_h0;
        float*       hn = (t & 1) ? g_h0 : g_h1;

        // A1: q partials (blocks 0..31) || gh cols 0..2047 partials (32..95)
        if (bid < 32) {
            skinny64(h, qW, Hh, (bid >> 1) * 64, (bid & 1) * 512,
                     g_qp + (size_t)(bid & 1) * (Bb * Hh), Hh, as, ws);
        } else {
            int tt = bid - 32;
            skinny64(h, Whh, Hh, (tt >> 1) * 64, (tt & 1) * 512,
                     g_ghp + (size_t)(tt & 1) * (Bb * G3), G3, as, ws);
        }
        grid_bar(++ep);

        // A2: scores. 3 blocks per batch; q folded into smem once per block.
        {
            int b = bid & 31, part = bid >> 5;
            const float* q0 = g_qp + (size_t)b * Hh;
            const float* q1 = g_qp + (size_t)(Bb * Hh) + (size_t)b * Hh;
            for (int j = tid; j < Hh; j += 256) qs[j] = q0[j] + q1[j] + qb[j];
            __syncthreads();
            int ss = part * 86;
            int se = ss + 86; if (se > SEe) se = SEe;
            const float4* qr = (const float4*)qs;
            for (int s = ss + warp; s < se; s += 8) {
                const float4* kr = (const float4*)(g_kT + ((size_t)b * SEe + s) * Hh);
                float a = 0.f;
#pragma unroll
                for (int i = 0; i < 8; i++) {
                    float4 kv = kr[lane + 32 * i];
                    float4 qv = qr[lane + 32 * i];
                    a += kv.x * qv.x + kv.y * qv.y + kv.z * qv.z + kv.w * qv.w;
                }
#pragma unroll
                for (int o = 16; o > 0; o >>= 1) a += __shfl_xor_sync(0xffffffffu, a, o);
                if (lane == 0) g_sc[b * SEe + s] = a;
            }
        }
        grid_bar(++ep);

        // A3: softmax + ctx halves (blocks 0..63) || gh cols 2048..3071 (64..95)
        if (bid < 64) {
            int b = bid >> 1, half = bid & 1;
            float v = g_sc[b * SEe + tid];
            float m = v;
#pragma unroll
            for (int o = 16; o > 0; o >>= 1) m = fmaxf(m, __shfl_xor_sync(0xffffffffu, m, o));
            if (lane == 0) red[warp] = m;
            __syncthreads();
            float mm = red[0];
#pragma unroll
            for (int i = 1; i < 8; i++) mm = fmaxf(mm, red[i]);
            float e = expf(v - mm);
            float ssum = e;
#pragma unroll
            for (int o = 16; o > 0; o >>= 1) ssum += __shfl_xor_sync(0xffffffffu, ssum, o);
            __syncthreads();
            if (lane == 0) red[warp] = ssum;
            __syncthreads();
            float tot = 0.f;
#pragma unroll
            for (int i = 0; i < 8; i++) tot += red[i];
            sc[tid] = e / tot;
            __syncthreads();

            int c0 = half * 512 + tid;
            float s0 = 0.f, s1 = 0.f;
#pragma unroll 4
            for (int s = 0; s < SEe; s++) {
                float a = sc[s];
                const float* er = g_enc_out + ((size_t)s * Bb + b) * Hh;
                s0 += a * er[c0];
                s1 += a * er[c0 + 256];
            }
            g_ctx[(size_t)b * Hh + c0]       = s0;
            g_ctx[(size_t)b * Hh + c0 + 256] = s1;
        } else {
            int tt = bid - 64;
            skinny64(h, Whh, Hh, 2048 + (tt >> 1) * 64, (tt & 1) * 512,
                     g_ghp + (size_t)(tt & 1) * (Bb * G3), G3, as, ws);
        }
        grid_bar(++ep);

        // A4: gc = ctx @ Wc.T partials (48 colgroups x 2 K-slices)
        skinny64(g_ctx, Wc, Ee + Hh, (bid >> 1) * 64, (bid & 1) * 512,
                 g_gcp + (size_t)(bid & 1) * (Bb * G3), G3, as, ws);
        grid_bar(++ep);

        // A5: gate + state update
        for (int idx = bid * 256 + tid; idx < Bb * Hh; idx += NBLK * 256) {
            int b = idx >> 10, j = idx & 1023;
            const float* gx  = g_dec_gx + (size_t)(t * Bb + b) * G3;
            const float* gh0 = g_ghp + (size_t)b * G3;
            const float* gh1 = g_ghp + (size_t)(Bb * G3) + (size_t)b * G3;
            const float* gc0 = g_gcp + (size_t)b * G3;
            const float* gc1 = g_gcp + (size_t)(Bb * G3) + (size_t)b * G3;
            float hr = gh0[j]        + gh1[j]        + bhh[j];
            float hz = gh0[Hh + j]   + gh1[Hh + j]   + bhh[Hh + j];
            float hv = gh0[2*Hh + j] + gh1[2*Hh + j] + bhh[2*Hh + j];
            float ir = gx[j]        + gc0[j]        + gc1[j];
            float iz = gx[Hh + j]   + gc0[Hh + j]   + gc1[Hh + j];
            float in = gx[2*Hh + j] + gc0[2*Hh + j] + gc1[2*Hh + j];
            float r = sigf(ir + hr);
            float z = sigf(iz + hz);
            float n = tanhf(in + r * hv);
            float hold = h[idx];
            float h2 = (1.f - z) * n + z * hold;
            hn[idx] = h2;
            g_dec_out[(size_t)t * Bb * Hh + idx] = h2;
        }
        grid_bar(++ep);
    }
}

extern "C" void kernel_launch(void* const* d_in, const int* in_sizes, int n_in,
                              void* d_out, int out_size)
{
    const int*   enc_in   = (const int*)d_in[0];
    const int*   dec_in   = (const int*)d_in[1];
    const int*   enc_len  = (const int*)d_in[2];
    const float* emb      = (const float*)d_in[4];
    const float* enc_Wih  = (const float*)d_in[5];
    const float* enc_Whh  = (const float*)d_in[6];
    const float* enc_bih  = (const float*)d_in[7];
    const float* enc_bhh  = (const float*)d_in[8];
    const float* dec_Wih  = (const float*)d_in[9];
    const float* dec_Whh  = (const float*)d_in[10];
    const float* dec_bih  = (const float*)d_in[11];
    const float* dec_bhh  = (const float*)d_in[12];
    const float* attn_kW  = (const float*)d_in[13];
    const float* attn_kb  = (const float*)d_in[14];
    const float* attn_qW  = (const float*)d_in[15];
    const float* attn_qb  = (const float*)d_in[16];
    const float* logits_W = (const float*)d_in[17];
    const float* logits_b = (const float*)d_in[18];
    float* out = (float*)d_out;
    (void)in_sizes; (void)n_in; (void)out_size;

    float *p_enc_gi, *p_dec_gx, *p_enc_out, *p_kT, *p_dec_out;
    int *p_enc_rows, *p_dec_rows;
    cudaGetSymbolAddress((void**)&p_enc_gi,  g_enc_gi);
    cudaGetSymbolAddress((void**)&p_dec_gx,  g_dec_gx);
    cudaGetSymbolAddress((void**)&p_enc_out, g_enc_out);
    cudaGetSymbolAddress((void**)&p_kT,      g_kT);
    cudaGetSymbolAddress((void**)&p_dec_out, g_dec_out);
    cudaGetSymbolAddress((void**)&p_enc_rows, g_enc_rows);
    cudaGetSymbolAddress((void**)&p_dec_rows, g_dec_rows);

    build_rows_kernel<<<32, 256>>>(enc_in, dec_in);
    init_h_kernel<<<(Bb * Hh) / 256, 256>>>();

    // hoisted input projections (embedding gather fused), tf32 tensor cores
    gemm_tf32<<<dim3(G3 / 128, (SEe * Bb) / 128), 256>>>(
        emb, p_enc_rows, Ee, enc_Wih, Ee, enc_bih, p_enc_gi, G3, Ee, 0);
    gemm_tf32<<<dim3(G3 / 128, (SDd * Bb) / 128), 256>>>(
        emb, p_dec_rows, Ee, dec_Wih, Ee + Hh, dec_bih, p_dec_gx, G3, Ee, 0);

    // encoder: 256 steps, one persistent launch (final state lands in g_h0)
    enc_persistent<<<NBLK, 256>>>(enc_Whh, enc_bhh, enc_len);

    // attention keys: (t,b,h) -> (b,s,h) via Sremap=SE
    gemm_tf32<<<dim3(Hh / 128, (SEe * Bb) / 128), 256>>>(
        p_enc_out, nullptr, Hh, attn_kW, Hh, attn_kb, p_kT, Hh, Hh, SEe);

    // decoder: 128 steps, one persistent launch
    dec_persistent<<<NBLK, 256>>>(attn_qW, attn_qb, dec_Whh, dec_Wih, dec_bhh);

    // logits: (t,b,h) @ W.T -> out[b*SD+t][v]  via Sremap=SD
    gemm_tf32<<<dim3(Vv / 128, (SDd * Bb) / 128), 256>>>(
        p_dec_out, nullptr, Hh, logits_W, Hh, logits_b, out, Vv, Hh, SDd);
}